// round 17
// baseline (speedup 1.0000x reference)
#include <cuda_runtime.h>
#include <cstdint>
#include <cstddef>

#define SEQ   2048
#define BATCH 128
#define HID   256
#define NCTA  128       // 64 clusters * 2 CTAs
#define HSTRIDE 132     // 128 cols + 4 pad floats (banks of the two halves disjoint)

// ---------------- f32x2 packed helpers (sm_103a) ----------------
__device__ __forceinline__ unsigned long long pk2(float x, float y){
    unsigned long long r; asm("mov.b64 %0, {%1,%2};" : "=l"(r) : "f"(x), "f"(y)); return r;
}
__device__ __forceinline__ void upk2(unsigned long long v, float& x, float& y){
    asm("mov.b64 {%0,%1}, %2;" : "=f"(x), "=f"(y) : "l"(v));
}
__device__ __forceinline__ unsigned long long ffma2(unsigned long long a,
                                                    unsigned long long b,
                                                    unsigned long long c){
    unsigned long long d;
    asm("fma.rn.f32x2 %0, %1, %2, %3;" : "=l"(d) : "l"(a), "l"(b), "l"(c));
    return d;
}

// ---------------- smem / cluster helpers (proven R5/R9/R15) ----------------
__device__ __forceinline__ unsigned smem_u32(const void* p){
    return (unsigned)__cvta_generic_to_shared(p);
}
__device__ __forceinline__ unsigned mapa_u32(unsigned laddr, unsigned peer){
    unsigned r;
    asm("mapa.shared::cluster.u32 %0, %1, %2;" : "=r"(r) : "r"(laddr), "r"(peer));
    return r;
}
__device__ __forceinline__ void mbar_init(unsigned a, unsigned cnt){
    asm volatile("mbarrier.init.shared.b64 [%0], %1;" :: "r"(a), "r"(cnt) : "memory");
}
__device__ __forceinline__ void mbar_inval(unsigned a){
    asm volatile("mbarrier.inval.shared.b64 [%0];" :: "r"(a) : "memory");
}
__device__ __forceinline__ void st_remote_f(unsigned raddr, float v){
    asm volatile("st.shared::cluster.b32 [%0], %1;" :: "r"(raddr), "f"(v) : "memory");
}
__device__ __forceinline__ void arrive_remote(unsigned raddr){
    asm volatile("mbarrier.arrive.release.cluster.shared::cluster.b64 _, [%0];"
                 :: "r"(raddr) : "memory");
}
__device__ __forceinline__ void mbar_wait_acq_cluster(unsigned a, unsigned parity){
    asm volatile(
        "{\n\t.reg .pred P;\n\t"
        "WL_%=:\n\t"
        "mbarrier.try_wait.parity.acquire.cluster.shared::cta.b64 P, [%0], %1, 0x989680;\n\t"
        "@!P bra WL_%=;\n\t"
        "}"
        :: "r"(a), "r"(parity) : "memory");
}
__device__ __forceinline__ void cluster_sync_hw(){
    asm volatile("barrier.cluster.arrive.aligned;" ::: "memory");
    asm volatile("barrier.cluster.wait.aligned;"   ::: "memory");
}
__device__ __forceinline__ unsigned cta_rank(){
    unsigned r; asm("mov.u32 %0, %%cluster_ctarank;" : "=r"(r)); return r;
}
__device__ __forceinline__ float sigmoidf(float x){
    return __fdividef(1.f, 1.f + __expf(-x));
}

// =====================================================================
// Persistent RNN + fused y epilogue. 64 clusters x 2 CTAs (256 thr),
// 2 batches/cluster. CTA r owns rows [r*128, r*128+128). Thread (w,l):
//   row iloc = w*16 + (l&15); col-half ch = l>>4 (pair lane l^16 = other half)
// Loop identical to the proven 2392/2400us structure; FFMA uses 8
// accumulator chains (m-parity split) for latency slack. After the loop
// the SAME kernel computes y for this CTA's batch (threadfence +
// cluster.sync flushes L1D / makes peer h-rows visible) -> single launch,
// so ncu's "-s 5 -c 1" window lands on rnn_kernel next round.
// =====================================================================
__global__ void __cluster_dims__(2,1,1) __launch_bounds__(256,1)
rnn_kernel(const float* __restrict__ x,      // (SEQ, BATCH)
           const float* __restrict__ h0,     // (BATCH, HID)
           const float* __restrict__ W_ih,   // (HID, 1)
           const float* __restrict__ W_hh,   // (HID, HID)
           const float* __restrict__ W_hhb,  // (HID, HID)
           const float* __restrict__ b_h,    // (HID,)
           const float* __restrict__ Wy,     // (2, HID) -> row 0 used
           const float* __restrict__ by,     // (2,)
           const void*  __restrict__ ctxp,   // scalar
           float* __restrict__ y,            // (BATCH, SEQ)
           float* __restrict__ outbuf)       // (BATCH, SEQ, HID)
{
    __shared__ __align__(16) float sa[2][2][2][HSTRIDE];   // [buf][batch][half][..]
    __shared__ float sx[SEQ * 2];
    __shared__ __align__(8) unsigned long long mb[2];

    const int t = (int)threadIdx.x;
    const int w = t >> 5, l = t & 31;
    const unsigned rank = cta_rank();
    const unsigned peer = rank ^ 1u;
    const int cid   = (int)blockIdx.x >> 1;
    const int b0    = cid * 2;
    const int iloc  = w * 16 + (l & 15);
    const int iglob = ((int)rank << 7) + iloc;
    const int ch    = l >> 4;

    float ctx;
    {
        int   iv = *(const int*)ctxp;
        float fv = *(const float*)ctxp;
        ctx = (iv >= -1000000 && iv <= 1000000) ? (float)iv : fv;
    }

    // ---- weights: row iglob, cols [ch*128, ch*128+128), f32x2-packed ----
    unsigned long long wreg[64];
    {
        const float4* wh = reinterpret_cast<const float4*>(W_hh  + (size_t)iglob * HID + ch * 128);
        const float4* wb = reinterpret_cast<const float4*>(W_hhb + (size_t)iglob * HID + ch * 128);
        #pragma unroll
        for (int m = 0; m < 32; ++m){
            float4 a4 = wh[m], c4 = wb[m];
            wreg[2*m]   = pk2(fmaf(ctx, c4.x, a4.x), fmaf(ctx, c4.y, a4.y));
            wreg[2*m+1] = pk2(fmaf(ctx, c4.z, a4.z), fmaf(ctx, c4.w, a4.w));
        }
    }
    const float win_r = W_ih[iglob];
    const float bh_r  = b_h[iglob];

    for (int idx = t; idx < SEQ * 2; idx += 256){
        sx[idx] = x[(size_t)(idx >> 1) * BATCH + b0 + (idx & 1)];
    }
    for (int idx = t; idx < 512; idx += 256){
        int bb = idx >> 8, c = idx & 255;
        sa[0][bb][c >> 7][c & 127] = fmaf(2.f, h0[(size_t)(b0 + bb) * HID + c], -1.f);
    }
    const unsigned mb_l = smem_u32(&mb[0]);
    if (t == 0){
        mbar_init(mb_l + 0u, 8);
        mbar_init(mb_l + 8u, 8);
    }
    __syncthreads();
    cluster_sync_hw();

    const unsigned sa_u32 = smem_u32(&sa[0][0][0][0]);
    const unsigned sa_r   = mapa_u32(sa_u32, peer);
    const unsigned mb_r   = mapa_u32(mb_l, peer);

    float* outp = outbuf + (size_t)(b0 + ch) * SEQ * HID + iglob;
    const unsigned aoff = (unsigned)((ch * 2 + (int)rank) * HSTRIDE + iloc) * 4u;
    const unsigned abuf = (unsigned)(2 * 2 * HSTRIDE) * 4u;

    int ph[2] = {0, 0};
    int cur = 0;

    for (int step = 0; step < SEQ; ++step){
        const int nxt = cur ^ 1;

        // ---- FFMA over my col-half, both batches; 8 accumulator chains ----
        const ulonglong2* a0p = reinterpret_cast<const ulonglong2*>(&sa[cur][0][ch][0]);
        const ulonglong2* a1p = reinterpret_cast<const ulonglong2*>(&sa[cur][1][ch][0]);
        unsigned long long acc[8] = {0ull,0ull,0ull,0ull,0ull,0ull,0ull,0ull};
        #pragma unroll
        for (int m = 0; m < 32; ++m){
            const int s = (m & 1) * 4;
            ulonglong2 A0 = a0p[m];
            ulonglong2 A1 = a1p[m];
            acc[s+0] = ffma2(wreg[2*m],   A0.x, acc[s+0]);
            acc[s+1] = ffma2(wreg[2*m+1], A0.y, acc[s+1]);
            acc[s+2] = ffma2(wreg[2*m],   A1.x, acc[s+2]);
            acc[s+3] = ffma2(wreg[2*m+1], A1.y, acc[s+3]);
        }
        float f0a,f0b,f1a,f1b,f2a,f2b,f3a,f3b;
        float g0a,g0b,g1a,g1b,g2a,g2b,g3a,g3b;
        upk2(acc[0], f0a, f0b); upk2(acc[1], f1a, f1b);
        upk2(acc[2], f2a, f2b); upk2(acc[3], f3a, f3b);
        upk2(acc[4], g0a, g0b); upk2(acc[5], g1a, g1b);
        upk2(acc[6], g2a, g2b); upk2(acc[7], g3a, g3b);
        float p0 = ((f0a + f0b) + (f1a + f1b)) + ((g0a + g0b) + (g1a + g1b));
        float p1 = ((f2a + f2b) + (f3a + f3b)) + ((g2a + g2b) + (g3a + g3b));
        float q0 = __shfl_xor_sync(0xFFFFFFFFu, p0, 16);
        float q1 = __shfl_xor_sync(0xFFFFFFFFu, p1, 16);
        float mysum = ch ? (p1 + q1) : (p0 + q0);

        // ---- finalize (row iglob, batch b0+ch) ----
        float pre = mysum + fmaf(sx[2*step + ch], win_r, bh_r);
        float hv  = sigmoidf(pre);
        outp[(size_t)step * HID] = hv;
        float av = fmaf(2.f, hv, -1.f);
        const unsigned dst = (unsigned)nxt * abuf + aoff;
        *reinterpret_cast<float*>(reinterpret_cast<char*>(&sa[0][0][0][0]) + dst) = av;

        __syncthreads();   // B2: done reading sa[cur]; local half of sa[nxt] visible

        st_remote_f(sa_r + dst, av);     // after BAR: no DSMEM drain on BAR path
        __syncwarp();
        if (l == 0) arrive_remote(mb_r + (unsigned)nxt * 8u);

        mbar_wait_acq_cluster(mb_l + (unsigned)nxt * 8u, (unsigned)ph[nxt]);
        ph[nxt] ^= 1;

        cur = nxt;
    }

    // ================= fused y epilogue =================
    // gpu-scope fence orders my h STGs to L2; cluster.sync waits for the
    // peer's fence and flushes L1D (CCTL.IVALL) so loads below see peer data.
    __threadfence();
    cluster_sync_hw();

    // This CTA computes y for batch (b0 + rank): 2048 rows, one warp per row.
    {
        const int bb = b0 + (int)rank;
        const float4* wp = reinterpret_cast<const float4*>(Wy);
        const float  bias = by[0];
        const float4 u = wp[l*2], v = wp[l*2 + 1];
        const float* base = outbuf + (size_t)bb * SEQ * HID;
        for (int row = w; row < SEQ; row += 8){
            const float4* p = reinterpret_cast<const float4*>(base + (size_t)row * HID);
            float4 a  = p[l*2];
            float4 c4 = p[l*2 + 1];
            float s = a.x*u.x + a.y*u.y + a.z*u.z + a.w*u.w
                    + c4.x*v.x + c4.y*v.y + c4.z*v.z + c4.w*v.w;
            #pragma unroll
            for (int off = 16; off; off >>= 1) s += __shfl_xor_sync(0xFFFFFFFFu, s, off);
            if (l == 0) y[(size_t)bb * SEQ + row] = s + bias;
        }
    }

    cluster_sync_hw();   // no CTA exits while peer may still write our smem
    if (t == 0){ mbar_inval(mb_l + 0u); mbar_inval(mb_l + 8u); }
}

extern "C" void kernel_launch(void* const* d_in, const int* in_sizes, int n_in,
                              void* d_out, int out_size)
{
    const float* x     = (const float*)d_in[0];
    const float* h0    = (const float*)d_in[1];
    const float* W_ih  = (const float*)d_in[2];
    const float* W_hh  = (const float*)d_in[3];
    const float* W_hhb = (const float*)d_in[4];
    const float* b_h   = (const float*)d_in[5];
    const float* W     = (const float*)d_in[6];
    const float* b     = (const float*)d_in[7];
    const void*  ctx   = d_in[8];

    float* y      = (float*)d_out;                 // (BATCH, SEQ)
    float* outbuf = y + (size_t)BATCH * SEQ;       // (BATCH, SEQ, HID)

    rnn_kernel<<<NCTA, 256>>>(x, h0, W_ih, W_hh, W_hhb, b_h, W, b, ctx, y, outbuf);
}